// round 1
// baseline (speedup 1.0000x reference)
#include <cuda_runtime.h>
#include <cuda_bf16.h>
#include <math.h>

#define Bb 32
#define Ss 512
#define Hh 256
#define BS (Bb*Ss)          // 16384 rows
#define KX 1024             // X columns: hb|ha|hh|wv
#define NG 1792             // 7 gates * 256

// ---------------- scratch (device globals; no allocation allowed) ----------------
__device__ float g_wv[BS*Hh];
__device__ float g_hh[2][BS*Hh];
__device__ float g_cs[2][BS*Hh];
__device__ float g_sv[2][Bb*Hh];
__device__ float g_scs[2][Bb*Hh];
__device__ float g_avg[Bb*Hh];
__device__ float g_fgsm[Bb*Hh];
__device__ float g_ogg[Bb*Hh];
__device__ float g_svproj[Bb*Hh];
__device__ float g_biasmat[Bb*NG];
__device__ float g_X[BS*KX];
__device__ float g_pre[BS*NG];
__device__ float g_sc[BS*Hh];
__device__ float g_Wcat[KX*NG];        // [k][g*256+h]
__device__ float g_Wgt[Hh*NG];         // W_g transposed  [k][g*256+h]
__device__ float g_Wfgih_t[Hh*Hh];     // W_fgi_h^T [k][h]

__device__ __forceinline__ float sigmoidf(float x){ return 1.f/(1.f+expf(-x)); }

// block-wide sum over 256 threads
__device__ __forceinline__ float block_sum_256(float v, float* sbuf){
    int lane = threadIdx.x & 31, w = threadIdx.x >> 5;
    #pragma unroll
    for (int o = 16; o > 0; o >>= 1) v += __shfl_xor_sync(0xffffffffu, v, o);
    if (lane == 0) sbuf[w] = v;
    __syncthreads();
    if (threadIdx.x < 32) {
        float r = (threadIdx.x < 8) ? sbuf[threadIdx.x] : 0.f;
        #pragma unroll
        for (int o = 4; o > 0; o >>= 1) r += __shfl_xor_sync(0xffffffffu, r, o);
        if (threadIdx.x == 0) sbuf[0] = r;
    }
    __syncthreads();
    float out = sbuf[0];
    __syncthreads();
    return out;
}

// ---------------- setup kernels ----------------
__global__ void k_gather(const int* __restrict__ idx, const float* __restrict__ embed){
    int m = blockIdx.x, h = threadIdx.x;
    g_wv[m*Hh + h] = embed[(size_t)idx[m]*Hh + h];
}

__global__ void k_init(const float* __restrict__ hh0, const float* __restrict__ cs0){
    int i = blockIdx.x*Hh + threadIdx.x;
    g_hh[0][i] = hh0[i];
    g_cs[0][i] = cs0[i];
}

__global__ void k_init_svscs(const float* __restrict__ hh0, const float* __restrict__ cs0){
    int b = blockIdx.x, h = threadIdx.x;
    float a = 0.f, c = 0.f;
    for (int s = 0; s < Ss; s++){
        a += hh0[(b*Ss+s)*Hh + h];
        c += cs0[(b*Ss+s)*Hh + h];
    }
    g_sv[0][b*Hh+h]  = a * (1.f/Ss);
    g_scs[0][b*Hh+h] = c * (1.f/Ss);
}

__global__ void k_wcat(const float* __restrict__ W_lr, const float* __restrict__ W_c,
                       const float* __restrict__ W_x){
    int k = blockIdx.x, g = blockIdx.y, h = threadIdx.x;
    float v;
    if (k < 512)      v = W_lr[((size_t)(g*Hh+h))*512 + k];
    else if (k < 768) v = W_c[((size_t)(g*Hh+h))*Hh + (k-512)];
    else              v = W_x[((size_t)(g*Hh+h))*Hh + (k-768)];
    g_Wcat[(size_t)k*NG + g*Hh + h] = v;
}

__global__ void k_wgt(const float* __restrict__ W_g){
    int k = blockIdx.x, g = blockIdx.y, h = threadIdx.x;
    g_Wgt[(size_t)k*NG + g*Hh + h] = W_g[((size_t)(g*Hh+h))*Hh + k];
}

__global__ void k_wfgih(const float* __restrict__ W_fgi_h){
    int k = blockIdx.x, h = threadIdx.x;
    g_Wfgih_t[k*Hh + h] = W_fgi_h[h*Hh + k];
}

// ---------------- per-layer kernels ----------------
__global__ void k_avg(int p){
    int b = blockIdx.x, h = threadIdx.x;
    const float* hh = g_hh[p];
    float a = 0.f;
    for (int s = 0; s < Ss; s++) a += hh[(b*Ss+s)*Hh + h];
    g_avg[b*Hh+h] = a * (1.f/Ss);
}

// sentence-level small gates: f_hat_g (softmaxed over H), og_g, sv@W_fgi_g^T
__global__ void k_small(const float* __restrict__ W_fg_g, const float* __restrict__ W_fg_h,
                        const float* __restrict__ W_og_g, const float* __restrict__ W_og_h,
                        const float* __restrict__ W_fgi_g, const float* __restrict__ b_fg,
                        const float* __restrict__ gate_bias, int p){
    __shared__ float ssv[Hh], sav[Hh];
    __shared__ float red[32];
    int b = blockIdx.x, h = threadIdx.x;
    ssv[h] = g_sv[p][b*Hh+h];
    sav[h] = g_avg[b*Hh+h];
    __syncthreads();
    float f  = b_fg[h];
    float o  = gate_bias[5*Hh + h];
    float sp = 0.f;
    const float* wfg = W_fg_g  + (size_t)h*Hh;
    const float* wfh = W_fg_h  + (size_t)h*Hh;
    const float* wog = W_og_g  + (size_t)h*Hh;
    const float* woh = W_og_h  + (size_t)h*Hh;
    const float* wfi = W_fgi_g + (size_t)h*Hh;
    for (int k = 0; k < Hh; k++){
        float s = ssv[k], a = sav[k];
        f  += s*wfg[k] + a*wfh[k];
        o  += s*wog[k] + a*woh[k];
        sp += s*wfi[k];
    }
    f = sigmoidf(f);
    o = sigmoidf(o);
    g_ogg[b*Hh+h]    = o;
    g_svproj[b*Hh+h] = sp;
    // softmax over h (sigmoid outputs in (0,1): shift-free exp is exact-equivalent)
    float e = expf(f);
    float tot = block_sum_256(e, red);
    g_fgsm[b*Hh+h] = e / tot;
}

// f_hat_g_i -> scores -> scores*cs, 8 rows per block
__global__ void __launch_bounds__(256) k_fgi(const float* __restrict__ b_fgi, int p){
    __shared__ float sh[8][Hh];
    __shared__ float red[32];
    int m0 = blockIdx.x * 8;
    int b  = m0 / Ss;
    int h  = threadIdx.x;
    const float* hh = g_hh[p];
    const float* cs = g_cs[p];
    #pragma unroll
    for (int j = 0; j < 8; j++) sh[j][h] = hh[(m0+j)*Hh + h];
    __syncthreads();
    float base = g_svproj[b*Hh+h] + b_fgi[h];
    float acc[8];
    #pragma unroll
    for (int j = 0; j < 8; j++) acc[j] = base;
    for (int k = 0; k < Hh; k++){
        float w = g_Wfgih_t[k*Hh + h];
        #pragma unroll
        for (int j = 0; j < 8; j++) acc[j] += sh[j][k] * w;
    }
    #pragma unroll
    for (int j = 0; j < 8; j++){
        float e = expf(sigmoidf(acc[j]));
        float tot = block_sum_256(e, red);
        g_sc[(m0+j)*Hh + h] = (e / tot) * cs[(m0+j)*Hh + h];
    }
}

// new_scs, new_sv
__global__ void k_scs(int p, int q){
    int b = blockIdx.x, h = threadIdx.x;
    float acc = 0.f;
    for (int s = 0; s < Ss; s++) acc += g_sc[(b*Ss+s)*Hh + h];
    int i = b*Hh + h;
    float ns = g_fgsm[i] * g_scs[p][i] + acc;
    g_scs[q][i] = ns;
    g_sv[q][i]  = g_ogg[i] * tanhf(ns);
}

// per-batch gate bias row: new_sv @ W_g^T + gate_bias  -> [Bb, NG]
__global__ void k_biasmat(const float* __restrict__ gate_bias, int q){
    __shared__ float ssv[Hh];
    int g = blockIdx.x, b = blockIdx.y, h = threadIdx.x;
    ssv[h] = g_sv[q][b*Hh + h];
    __syncthreads();
    int n = g*Hh + h;
    float acc = gate_bias[n];
    for (int k = 0; k < Hh; k++) acc += ssv[k] * g_Wgt[(size_t)k*NG + n];
    g_biasmat[(size_t)b*NG + n] = acc;
}

// X = [hb | ha | hh | wv]
__global__ void k_buildX(int p){
    int m = blockIdx.x, h = threadIdx.x;
    int s = m % Ss;
    const float* hh = g_hh[p];
    float hb = 0.f, ha = 0.f;
    if (s >= 1)    hb += hh[(m-1)*Hh + h];
    if (s >= 2)    hb += hh[(m-2)*Hh + h];
    if (s+1 < Ss)  ha += hh[(m+1)*Hh + h];
    if (s+2 < Ss)  ha += hh[(m+2)*Hh + h];
    float* X = g_X + (size_t)m*KX;
    X[h]        = hb;
    X[256 + h]  = ha;
    X[512 + h]  = hh[m*Hh + h];
    X[768 + h]  = g_wv[m*Hh + h];
}

// big GEMM: pre = X (16384x1024) @ Wcat (1024x1792) + biasmat[b]
__global__ void __launch_bounds__(256) k_gemm(){
    const int K = KX, N = NG;
    __shared__ float As[16][128];
    __shared__ float Bs[16][128];
    int bn = blockIdx.x, bm = blockIdx.y;
    int tid = threadIdx.x;
    const float* A  = g_X    + (size_t)(bm*128)*K;
    const float* Bp = g_Wcat + bn*128;
    float acc[8][8];
    #pragma unroll
    for (int i = 0; i < 8; i++)
        #pragma unroll
        for (int j = 0; j < 8; j++) acc[i][j] = 0.f;

    int arow = tid >> 2, ac4 = tid & 3;    // A: 64 rows x 4 float4 per pass
    int brow = tid >> 5, bc4 = tid & 31;   // B: 8 k-rows x 32 float4 per pass
    int ty = tid >> 4, tx = tid & 15;

    for (int k0 = 0; k0 < K; k0 += 16){
        #pragma unroll
        for (int i = 0; i < 2; i++){
            int r = arow + i*64;
            float4 v = *(const float4*)(A + (size_t)r*K + k0 + ac4*4);
            As[ac4*4+0][r] = v.x; As[ac4*4+1][r] = v.y;
            As[ac4*4+2][r] = v.z; As[ac4*4+3][r] = v.w;
        }
        #pragma unroll
        for (int i = 0; i < 2; i++){
            int r = brow + i*8;
            float4 v = *(const float4*)(Bp + (size_t)(k0+r)*N + bc4*4);
            *(float4*)&Bs[r][bc4*4] = v;
        }
        __syncthreads();
        #pragma unroll
        for (int kk = 0; kk < 16; kk++){
            float4 a0 = *(const float4*)&As[kk][ty*8];
            float4 a1 = *(const float4*)&As[kk][ty*8+4];
            float4 b0 = *(const float4*)&Bs[kk][tx*8];
            float4 b1 = *(const float4*)&Bs[kk][tx*8+4];
            float ar[8] = {a0.x,a0.y,a0.z,a0.w,a1.x,a1.y,a1.z,a1.w};
            float br[8] = {b0.x,b0.y,b0.z,b0.w,b1.x,b1.y,b1.z,b1.w};
            #pragma unroll
            for (int i = 0; i < 8; i++)
                #pragma unroll
                for (int j = 0; j < 8; j++) acc[i][j] += ar[i]*br[j];
        }
        __syncthreads();
    }
    int b = (bm*128) / Ss;    // 512 % 128 == 0: tile within one batch row
    const float* bias = g_biasmat + (size_t)b*N + bn*128 + tx*8;
    float4 bv0 = *(const float4*)(bias);
    float4 bv1 = *(const float4*)(bias + 4);
    float bb[8] = {bv0.x,bv0.y,bv0.z,bv0.w,bv1.x,bv1.y,bv1.z,bv1.w};
    #pragma unroll
    for (int i = 0; i < 8; i++){
        int row = bm*128 + ty*8 + i;
        float* Cp = g_pre + (size_t)row*N + bn*128 + tx*8;
        float4 o0, o1;
        o0.x = acc[i][0]+bb[0]; o0.y = acc[i][1]+bb[1];
        o0.z = acc[i][2]+bb[2]; o0.w = acc[i][3]+bb[3];
        o1.x = acc[i][4]+bb[4]; o1.y = acc[i][5]+bb[5];
        o1.z = acc[i][6]+bb[6]; o1.w = acc[i][7]+bb[7];
        *(float4*)(Cp)     = o0;
        *(float4*)(Cp + 4) = o1;
    }
}

// activations + state update
__global__ void k_act(int p, int q){
    __shared__ float red[32];
    int m = blockIdx.x, h = threadIdx.x;
    int b = m / Ss, s = m % Ss;
    const float* pr = g_pre + (size_t)m*NG;
    float eg[5];
    float esum = 0.f;
    #pragma unroll
    for (int g = 0; g < 5; g++){
        float v = sigmoidf(pr[g*Hh + h]);
        eg[g] = expf(v);
        esum += eg[g];
    }
    float og = sigmoidf(pr[5*Hh + h]);
    float u  = tanhf(pr[6*Hh + h]);
    float tot = block_sum_256(esum, red);
    float inv = 1.f / tot;
    const float* cs = g_cs[p];
    float cb = 0.f, ca = 0.f;
    if (s >= 1)   cb += cs[(m-1)*Hh + h];
    if (s >= 2)   cb += cs[(m-2)*Hh + h];
    if (s+1 < Ss) ca += cs[(m+1)*Hh + h];
    if (s+2 < Ss) ca += cs[(m+2)*Hh + h];
    float i_t = eg[0]*inv, l_t = eg[1]*inv, r_t = eg[2]*inv, f_t = eg[3]*inv, s_t = eg[4]*inv;
    float ncs = l_t*cb + f_t*cs[m*Hh+h] + r_t*ca + s_t*g_scs[p][b*Hh+h] + i_t*u;
    g_cs[q][m*Hh+h] = ncs;
    g_hh[q][m*Hh+h] = og * tanhf(ncs);
}

// output head
__global__ void k_head(const float* __restrict__ W1, const float* __restrict__ b1,
                       const float* __restrict__ Wout, const float* __restrict__ bout,
                       int p, float* __restrict__ out, int out_size){
    __shared__ float sa[Hh], ssv[Hh], conc[Hh], fc[5];
    __shared__ float lse;
    int b = blockIdx.x, h = threadIdx.x;
    sa[h]  = g_avg[b*Hh + h];
    ssv[h] = g_sv[p][b*Hh + h];
    __syncthreads();
    float c = b1[h];
    const float* w = W1 + (size_t)h*512;
    for (int k = 0; k < Hh; k++) c += sa[k]  * w[k];
    for (int k = 0; k < Hh; k++) c += ssv[k] * w[256 + k];
    conc[h] = c;
    __syncthreads();
    if (h < 5){
        float f = bout[h];
        const float* wo = Wout + (size_t)h*Hh;
        for (int k = 0; k < Hh; k++) f += conc[k]*wo[k];
        fc[h] = f;
    }
    __syncthreads();
    if (h == 0){
        float mx = fc[0];
        #pragma unroll
        for (int i = 1; i < 5; i++) mx = fmaxf(mx, fc[i]);
        float sum = 0.f;
        #pragma unroll
        for (int i = 0; i < 5; i++) sum += expf(fc[i] - mx);
        lse = mx + logf(sum);
    }
    __syncthreads();
    if (h < 5 && out_size >= Bb*5) out[b*5 + h] = fc[h] - lse;
    if (out_size >= Bb*5 + Bb*Hh)  out[Bb*5 + b*Hh + h] = ssv[h];
}

// ---------------- host ----------------
extern "C" void kernel_launch(void* const* d_in, const int* in_sizes, int n_in,
                              void* d_out, int out_size){
    const int*   idx       = (const int*)  d_in[0];
    // d_in[1] = sentences_length (unused by reference)
    const float* hh0       = (const float*)d_in[2];
    const float* cs0       = (const float*)d_in[3];
    const float* embed     = (const float*)d_in[4];
    const float* W_lr      = (const float*)d_in[5];
    const float* W_c       = (const float*)d_in[6];
    const float* W_x       = (const float*)d_in[7];
    const float* W_g       = (const float*)d_in[8];
    const float* gate_bias = (const float*)d_in[9];
    const float* W_fg_g    = (const float*)d_in[10];
    const float* W_fg_h    = (const float*)d_in[11];
    const float* W_fgi_g   = (const float*)d_in[12];
    const float* W_fgi_h   = (const float*)d_in[13];
    const float* W_og_g    = (const float*)d_in[14];
    const float* W_og_h    = (const float*)d_in[15];
    const float* b_fg      = (const float*)d_in[16];
    const float* b_fgi     = (const float*)d_in[17];
    const float* W1        = (const float*)d_in[18];
    const float* b1        = (const float*)d_in[19];
    const float* Wout      = (const float*)d_in[20];
    const float* bout      = (const float*)d_in[21];
    float* out = (float*)d_out;

    k_gather<<<BS, Hh>>>(idx, embed);
    k_wcat<<<dim3(KX, 7), Hh>>>(W_lr, W_c, W_x);
    k_wgt<<<dim3(Hh, 7), Hh>>>(W_g);
    k_wfgih<<<Hh, Hh>>>(W_fgi_h);
    k_init<<<BS, Hh>>>(hh0, cs0);
    k_init_svscs<<<Bb, Hh>>>(hh0, cs0);

    int p = 0;
    for (int layer = 0; layer < 2; layer++){
        int q = 1 - p;
        k_avg<<<Bb, Hh>>>(p);
        k_small<<<Bb, Hh>>>(W_fg_g, W_fg_h, W_og_g, W_og_h, W_fgi_g, b_fg, gate_bias, p);
        k_fgi<<<BS/8, Hh>>>(b_fgi, p);
        k_scs<<<Bb, Hh>>>(p, q);
        k_biasmat<<<dim3(7, Bb), Hh>>>(gate_bias, q);
        k_buildX<<<BS, Hh>>>(p);
        k_gemm<<<dim3(NG/128, BS/128), 256>>>();
        k_act<<<BS, Hh>>>(p, q);
        p = q;
    }
    k_avg<<<Bb, Hh>>>(p);
    k_head<<<Bb, Hh>>>(W1, b1, Wout, bout, p, out, out_size);
}

// round 3
// speedup vs baseline: 1.4374x; 1.4374x over previous
#include <cuda_runtime.h>
#include <cuda_bf16.h>
#include <math.h>
#include <stdint.h>

#define Bb 32
#define Ss 512
#define Hh 256
#define BS (Bb*Ss)          // 16384 rows
#define NG 1792             // 7 gates * 256
#define KS 2048             // stored K columns (hi | lo)
#define KIT 96              // K' = 3072 in 96 chunks of 32
#define A_ROWB 80           // padded smem row stride (32 bf16 = 64B -> 80B)
#define A_SZ (128*A_ROWB)   // 10240
#define B_SZ (256*A_ROWB)   // 20480
#define ST_SZ (A_SZ + B_SZ) // 30720
#define SMEM_MMA (4*ST_SZ + 256)
#define NTILE 896           // 7 (n) x 128 (m)

// ---------------- scratch (device globals; no allocation allowed) ----------------
__device__ float g_wv[BS*Hh];
__device__ float g_hh[2][BS*Hh];
__device__ float g_cs[2][BS*Hh];
__device__ float g_sv[2][Bb*Hh];
__device__ float g_scs[2][Bb*Hh];
__device__ float g_avg[Bb*Hh];
__device__ float g_fgsm[Bb*Hh];
__device__ float g_ogg[Bb*Hh];
__device__ float g_svproj[Bb*Hh];
__device__ float g_biasmat[Bb*NG];
__device__ float g_pre[(size_t)BS*NG];
__device__ float g_sc[BS*Hh];
__device__ float g_Wgt[Hh*NG];         // W_g transposed  [k][g*256+h]
__device__ float g_Wfgih_t[Hh*Hh];     // W_fgi_h^T [k][h]
__device__ __align__(16) __nv_bfloat16 g_Xs[(size_t)BS*KS];   // [m][ hi(1024) | lo(1024) ]
__device__ __align__(16) __nv_bfloat16 g_Wn[(size_t)NG*KS];   // [n][ hi(1024) | lo(1024) ]

__device__ __forceinline__ float sigmoidf(float x){ return 1.f/(1.f+expf(-x)); }

__device__ __forceinline__ uint32_t smem_u32(const void* p){
    uint32_t a;
    asm("{ .reg .u64 t; cvta.to.shared.u64 t, %1; cvt.u32.u64 %0, t; }" : "=r"(a) : "l"(p));
    return a;
}

__device__ __forceinline__ void ldsm4(uint32_t (&r)[4], uint32_t a){
    asm volatile("ldmatrix.sync.aligned.m8n8.x4.shared.b16 {%0,%1,%2,%3}, [%4];"
        : "=r"(r[0]), "=r"(r[1]), "=r"(r[2]), "=r"(r[3]) : "r"(a));
}

__device__ __forceinline__ void mma16816(float (&c)[4], const uint32_t (&a)[4],
                                         uint32_t b0, uint32_t b1){
    asm volatile("mma.sync.aligned.m16n8k16.row.col.f32.bf16.bf16.f32 "
        "{%0,%1,%2,%3}, {%4,%5,%6,%7}, {%8,%9}, {%0,%1,%2,%3};"
        : "+f"(c[0]), "+f"(c[1]), "+f"(c[2]), "+f"(c[3])
        : "r"(a[0]), "r"(a[1]), "r"(a[2]), "r"(a[3]), "r"(b0), "r"(b1));
}

// block-wide sum over 256 threads
__device__ __forceinline__ float block_sum_256(float v, float* sbuf){
    int lane = threadIdx.x & 31, w = threadIdx.x >> 5;
    #pragma unroll
    for (int o = 16; o > 0; o >>= 1) v += __shfl_xor_sync(0xffffffffu, v, o);
    if (lane == 0) sbuf[w] = v;
    __syncthreads();
    if (threadIdx.x < 32) {
        float r = (threadIdx.x < 8) ? sbuf[threadIdx.x] : 0.f;
        #pragma unroll
        for (int o = 4; o > 0; o >>= 1) r += __shfl_xor_sync(0xffffffffu, r, o);
        if (threadIdx.x == 0) sbuf[0] = r;
    }
    __syncthreads();
    float out = sbuf[0];
    __syncthreads();
    return out;
}

// ---------------- setup kernels ----------------
__global__ void k_gather(const int* __restrict__ idx, const float* __restrict__ embed){
    int m = blockIdx.x, h = threadIdx.x;
    g_wv[m*Hh + h] = embed[(size_t)idx[m]*Hh + h];
}

__global__ void k_init(const float* __restrict__ hh0, const float* __restrict__ cs0){
    int i = blockIdx.x*Hh + threadIdx.x;
    g_hh[0][i] = hh0[i];
    g_cs[0][i] = cs0[i];
}

__global__ void k_init_svscs(const float* __restrict__ hh0, const float* __restrict__ cs0){
    int b = blockIdx.x, h = threadIdx.x;
    float a = 0.f, c = 0.f;
    for (int s = 0; s < Ss; s++){
        a += hh0[(b*Ss+s)*Hh + h];
        c += cs0[(b*Ss+s)*Hh + h];
    }
    g_sv[0][b*Hh+h]  = a * (1.f/Ss);
    g_scs[0][b*Hh+h] = c * (1.f/Ss);
}

// split W = [W_lr | W_c | W_x] rows into bf16 hi|lo, stored N-major [1792][2048]
__global__ void k_wsplit(const float* __restrict__ W_lr, const float* __restrict__ W_c,
                         const float* __restrict__ W_x){
    int n = blockIdx.x;            // 0..1791
    int g = n >> 8, h = n & 255;
    for (int k = threadIdx.x; k < 1024; k += 256){
        float v;
        if (k < 512)      v = W_lr[((size_t)g*Hh + h)*512 + k];
        else if (k < 768) v = W_c[((size_t)g*Hh + h)*Hh + (k-512)];
        else              v = W_x[((size_t)g*Hh + h)*Hh + (k-768)];
        __nv_bfloat16 hi = __float2bfloat16(v);
        __nv_bfloat16 lo = __float2bfloat16(v - __bfloat162float(hi));
        g_Wn[(size_t)n*KS + k]        = hi;
        g_Wn[(size_t)n*KS + 1024 + k] = lo;
    }
}

__global__ void k_wgt(const float* __restrict__ W_g){
    int k = blockIdx.x, g = blockIdx.y, h = threadIdx.x;
    g_Wgt[(size_t)k*NG + g*Hh + h] = W_g[((size_t)(g*Hh+h))*Hh + k];
}

__global__ void k_wfgih(const float* __restrict__ W_fgi_h){
    int k = blockIdx.x, h = threadIdx.x;
    g_Wfgih_t[k*Hh + h] = W_fgi_h[h*Hh + k];
}

// ---------------- per-layer kernels ----------------
__global__ void k_avg(int p){
    int b = blockIdx.x, h = threadIdx.x;
    const float* hh = g_hh[p];
    float a = 0.f;
    for (int s = 0; s < Ss; s++) a += hh[(b*Ss+s)*Hh + h];
    g_avg[b*Hh+h] = a * (1.f/Ss);
}

__global__ void k_small(const float* __restrict__ W_fg_g, const float* __restrict__ W_fg_h,
                        const float* __restrict__ W_og_g, const float* __restrict__ W_og_h,
                        const float* __restrict__ W_fgi_g, const float* __restrict__ b_fg,
                        const float* __restrict__ gate_bias, int p){
    __shared__ float ssv[Hh], sav[Hh];
    __shared__ float red[32];
    int b = blockIdx.x, h = threadIdx.x;
    ssv[h] = g_sv[p][b*Hh+h];
    sav[h] = g_avg[b*Hh+h];
    __syncthreads();
    float f  = b_fg[h];
    float o  = gate_bias[5*Hh + h];
    float sp = 0.f;
    const float* wfg = W_fg_g  + (size_t)h*Hh;
    const float* wfh = W_fg_h  + (size_t)h*Hh;
    const float* wog = W_og_g  + (size_t)h*Hh;
    const float* woh = W_og_h  + (size_t)h*Hh;
    const float* wfi = W_fgi_g + (size_t)h*Hh;
    for (int k = 0; k < Hh; k++){
        float s = ssv[k], a = sav[k];
        f  += s*wfg[k] + a*wfh[k];
        o  += s*wog[k] + a*woh[k];
        sp += s*wfi[k];
    }
    f = sigmoidf(f);
    o = sigmoidf(o);
    g_ogg[b*Hh+h]    = o;
    g_svproj[b*Hh+h] = sp;
    float e = expf(f);
    float tot = block_sum_256(e, red);
    g_fgsm[b*Hh+h] = e / tot;
}

__global__ void __launch_bounds__(256) k_fgi(const float* __restrict__ b_fgi, int p){
    __shared__ float sh[8][Hh];
    __shared__ float red[32];
    int m0 = blockIdx.x * 8;
    int b  = m0 / Ss;
    int h  = threadIdx.x;
    const float* hh = g_hh[p];
    const float* cs = g_cs[p];
    #pragma unroll
    for (int j = 0; j < 8; j++) sh[j][h] = hh[(m0+j)*Hh + h];
    __syncthreads();
    float base = g_svproj[b*Hh+h] + b_fgi[h];
    float acc[8];
    #pragma unroll
    for (int j = 0; j < 8; j++) acc[j] = base;
    for (int k = 0; k < Hh; k++){
        float w = g_Wfgih_t[k*Hh + h];
        #pragma unroll
        for (int j = 0; j < 8; j++) acc[j] += sh[j][k] * w;
    }
    #pragma unroll
    for (int j = 0; j < 8; j++){
        float e = expf(sigmoidf(acc[j]));
        float tot = block_sum_256(e, red);
        g_sc[(m0+j)*Hh + h] = (e / tot) * cs[(m0+j)*Hh + h];
    }
}

__global__ void k_scs(int p, int q){
    int b = blockIdx.x, h = threadIdx.x;
    float acc = 0.f;
    for (int s = 0; s < Ss; s++) acc += g_sc[(b*Ss+s)*Hh + h];
    int i = b*Hh + h;
    float ns = g_fgsm[i] * g_scs[p][i] + acc;
    g_scs[q][i] = ns;
    g_sv[q][i]  = g_ogg[i] * tanhf(ns);
}

__global__ void k_biasmat(const float* __restrict__ gate_bias, int q){
    __shared__ float ssv[Hh];
    int g = blockIdx.x, b = blockIdx.y, h = threadIdx.x;
    ssv[h] = g_sv[q][b*Hh + h];
    __syncthreads();
    int n = g*Hh + h;
    float acc = gate_bias[n];
    for (int k = 0; k < Hh; k++) acc += ssv[k] * g_Wgt[(size_t)k*NG + n];
    g_biasmat[(size_t)b*NG + n] = acc;
}

// X = [hb | ha | hh | wv] split into bf16 hi|lo -> g_Xs [m][2048]
__global__ void k_buildXs(int p){
    int m = blockIdx.x, h = threadIdx.x;
    int s = m % Ss;
    const float* hh = g_hh[p];
    float hb = 0.f, ha = 0.f;
    if (s >= 1)    hb += hh[(m-1)*Hh + h];
    if (s >= 2)    hb += hh[(m-2)*Hh + h];
    if (s+1 < Ss)  ha += hh[(m+1)*Hh + h];
    if (s+2 < Ss)  ha += hh[(m+2)*Hh + h];
    float vals[4];
    vals[0] = hb;
    vals[1] = ha;
    vals[2] = hh[m*Hh + h];
    vals[3] = g_wv[m*Hh + h];
    __nv_bfloat16* X = g_Xs + (size_t)m*KS;
    #pragma unroll
    for (int j = 0; j < 4; j++){
        int c = j*256 + h;
        __nv_bfloat16 hi = __float2bfloat16(vals[j]);
        __nv_bfloat16 lo = __float2bfloat16(vals[j] - __bfloat162float(hi));
        X[c]        = hi;
        X[1024 + c] = lo;
    }
}

// ---------------- HMMA GEMM: pre = Xsplit @ Wsplit^T + biasmat ----------------
// persistent, CTA tile 128x256, BK=32, 4-stage cp.async, 8 warps of 64x64 (m16n8k16)
__global__ void __launch_bounds__(256,1) k_mma(){
    extern __shared__ char smc[];
    uint32_t dbase = (smem_u32(smc) + 127) & ~127u;
    int tid = threadIdx.x, wid = tid >> 5, lane = tid & 31;
    int wm = wid >> 2, wn = wid & 3;

    // ldmatrix per-lane components
    uint32_t aLane = (uint32_t)(wm*64 + (lane & 15))*A_ROWB + (uint32_t)(lane >> 4)*16;
    uint32_t bLane = (uint32_t)(wn*64 + ((lane >> 4) << 3) + (lane & 7))*A_ROWB
                   + (uint32_t)((lane >> 3) & 1)*16;

    for (int tile = blockIdx.x; tile < NTILE; tile += gridDim.x){
        int bn = tile % 7, bm = tile / 7;
        const __nv_bfloat16* Ag = g_Xs + (size_t)(bm*128)*KS;
        const __nv_bfloat16* Bg = g_Wn + (size_t)(bn*256)*KS;

        float acc[4][8][4];
        #pragma unroll
        for (int i = 0; i < 4; i++)
            #pragma unroll
            for (int j = 0; j < 8; j++)
                #pragma unroll
                for (int r = 0; r < 4; r++) acc[i][j][r] = 0.f;

        auto load_chunk = [&](int t){
            if (t < KIT){
                int s = t & 3;
                uint32_t sA = dbase + s*ST_SZ;
                uint32_t sB = sA + A_SZ;
                int aoff = (t < 32) ? t*32 : (t < 64) ? 1024 + (t-32)*32 : (t-64)*32;
                int boff = (t < 64) ? (t & 31)*32 : 1024 + (t-64)*32;
                #pragma unroll
                for (int i = 0; i < 2; i++){
                    int idx = tid + i*256;
                    int r = idx >> 2, c = idx & 3;
                    asm volatile("cp.async.cg.shared.global [%0], [%1], 16;"
                        :: "r"(sA + r*A_ROWB + c*16), "l"(Ag + (size_t)r*KS + aoff + c*8));
                }
                #pragma unroll
                for (int i = 0; i < 4; i++){
                    int idx = tid + i*256;
                    int r = idx >> 2, c = idx & 3;
                    asm volatile("cp.async.cg.shared.global [%0], [%1], 16;"
                        :: "r"(sB + r*A_ROWB + c*16), "l"(Bg + (size_t)r*KS + boff + c*8));
                }
            }
            asm volatile("cp.async.commit_group;" ::: "memory");
        };

        __syncthreads();                // previous tile's readers done
        load_chunk(0); load_chunk(1); load_chunk(2);

        for (int t = 0; t < KIT; t++){
            asm volatile("cp.async.wait_group 2;" ::: "memory");
            __syncthreads();
            load_chunk(t + 3);

            int s = t & 3;
            uint32_t sA = dbase + s*ST_SZ + aLane;
            uint32_t sB = dbase + s*ST_SZ + A_SZ + bLane;
            #pragma unroll
            for (int ks = 0; ks < 2; ks++){
                uint32_t afr[4][4], bfr[4][4];
                #pragma unroll
                for (int mi = 0; mi < 4; mi++)
                    ldsm4(afr[mi], sA + mi*(16*A_ROWB) + ks*32);
                #pragma unroll
                for (int njp = 0; njp < 4; njp++)
                    ldsm4(bfr[njp], sB + njp*(16*A_ROWB) + ks*32);
                #pragma unroll
                for (int mi = 0; mi < 4; mi++){
                    #pragma unroll
                    for (int njp = 0; njp < 4; njp++){
                        mma16816(acc[mi][2*njp],   afr[mi], bfr[njp][0], bfr[njp][1]);
                        mma16816(acc[mi][2*njp+1], afr[mi], bfr[njp][2], bfr[njp][3]);
                    }
                }
            }
        }

        // epilogue: add biasmat, store fp32
        int b = bm >> 2;                       // 4 M-tiles per batch row
        int colbase = bn*256 + wn*64;
        const float* bias = g_biasmat + (size_t)b*NG + colbase;
        #pragma unroll
        for (int mi = 0; mi < 4; mi++){
            int r0 = bm*128 + wm*64 + mi*16 + (lane >> 2);
            float* out0 = g_pre + (size_t)r0*NG + colbase;
            float* out1 = g_pre + (size_t)(r0+8)*NG + colbase;
            #pragma unroll
            for (int nj = 0; nj < 8; nj++){
                int col = nj*8 + (lane & 3)*2;
                float2 bv = *(const float2*)(bias + col);
                float2 o0, o1;
                o0.x = acc[mi][nj][0] + bv.x; o0.y = acc[mi][nj][1] + bv.y;
                o1.x = acc[mi][nj][2] + bv.x; o1.y = acc[mi][nj][3] + bv.y;
                *(float2*)(out0 + col) = o0;
                *(float2*)(out1 + col) = o1;
            }
        }
    }
}

// activations + state update
__global__ void k_act(int p, int q){
    __shared__ float red[32];
    int m = blockIdx.x, h = threadIdx.x;
    int b = m / Ss, s = m % Ss;
    const float* pr = g_pre + (size_t)m*NG;
    float eg[5];
    float esum = 0.f;
    #pragma unroll
    for (int g = 0; g < 5; g++){
        float v = sigmoidf(pr[g*Hh + h]);
        eg[g] = expf(v);
        esum += eg[g];
    }
    float og = sigmoidf(pr[5*Hh + h]);
    float u  = tanhf(pr[6*Hh + h]);
    float tot = block_sum_256(esum, red);
    float inv = 1.f / tot;
    const float* cs = g_cs[p];
    float cb = 0.f, ca = 0.f;
    if (s >= 1)   cb += cs[(m-1)*Hh + h];
    if (s >= 2)   cb += cs[(m-2)*Hh + h];
    if (s+1 < Ss) ca += cs[(m+1)*Hh + h];
    if (s+2 < Ss) ca += cs[(m+2)*Hh + h];
    float i_t = eg[0]*inv, l_t = eg[1]*inv, r_t = eg[2]*inv, f_t = eg[3]*inv, s_t = eg[4]*inv;
    float ncs = l_t*cb + f_t*cs[m*Hh+h] + r_t*ca + s_t*g_scs[p][b*Hh+h] + i_t*u;
    g_cs[q][m*Hh+h] = ncs;
    g_hh[q][m*Hh+h] = og * tanhf(ncs);
}

// output head
__global__ void k_head(const float* __restrict__ W1, const float* __restrict__ b1,
                       const float* __restrict__ Wout, const float* __restrict__ bout,
                       int p, float* __restrict__ out, int out_size){
    __shared__ float sa[Hh], ssv[Hh], conc[Hh], fc[5];
    __shared__ float lse;
    int b = blockIdx.x, h = threadIdx.x;
    sa[h]  = g_avg[b*Hh + h];
    ssv[h] = g_sv[p][b*Hh + h];
    __syncthreads();
    float c = b1[h];
    const float* w = W1 + (size_t)h*512;
    for (int k = 0; k < Hh; k++) c += sa[k]  * w[k];
    for (int k = 0; k < Hh; k++) c += ssv[k] * w[256 + k];
    conc[h] = c;
    __syncthreads();
    if (h < 5){
        float f = bout[h];
        const float* wo = Wout + (size_t)h*Hh;
        for (int k = 0; k < Hh; k++) f += conc[k]*wo[k];
        fc[h] = f;
    }
    __syncthreads();
    if (h == 0){
        float mx = fc[0];
        #pragma unroll
        for (int i = 1; i < 5; i++) mx = fmaxf(mx, fc[i]);
        float sum = 0.f;
        #pragma unroll
        for (int i = 0; i < 5; i++) sum += expf(fc[i] - mx);
        lse = mx + logf(sum);
    }
    __syncthreads();
    if (h < 5 && out_size >= Bb*5) out[b*5 + h] = fc[h] - lse;
    if (out_size >= Bb*5 + Bb*Hh)  out[Bb*5 + b*Hh + h] = ssv[h];
}

// ---------------- host ----------------
extern "C" void kernel_launch(void* const* d_in, const int* in_sizes, int n_in,
                              void* d_out, int out_size){
    const int*   idx       = (const int*)  d_in[0];
    const float* hh0       = (const float*)d_in[2];
    const float* cs0       = (const float*)d_in[3];
    const float* embed     = (const float*)d_in[4];
    const float* W_lr      = (const float*)d_in[5];
    const float* W_c       = (const float*)d_in[6];
    const float* W_x       = (const float*)d_in[7];
    const float* W_g       = (const float*)d_in[8];
    const float* gate_bias = (const float*)d_in[9];
    const float* W_fg_g    = (const float*)d_in[10];
    const float* W_fg_h    = (const float*)d_in[11];
    const float* W_fgi_g   = (const float*)d_in[12];
    const float* W_fgi_h   = (const float*)d_in[13];
    const float* W_og_g    = (const float*)d_in[14];
    const float* W_og_h    = (const float*)d_in[15];
    const float* b_fg      = (const float*)d_in[16];
    const float* b_fgi     = (const float*)d_in[17];
    const float* W1        = (const float*)d_in[18];
    const float* b1        = (const float*)d_in[19];
    const float* Wout      = (const float*)d_in[20];
    const float* bout      = (const float*)d_in[21];
    float* out = (float*)d_out;

    cudaFuncSetAttribute(k_mma, cudaFuncAttributeMaxDynamicSharedMemorySize, SMEM_MMA);

    k_gather<<<BS, Hh>>>(idx, embed);
    k_wsplit<<<NG, 256>>>(W_lr, W_c, W_x);
    k_wgt<<<dim3(Hh, 7), Hh>>>(W_g);
    k_wfgih<<<Hh, Hh>>>(W_fgi_h);
    k_init<<<BS, Hh>>>(hh0, cs0);
    k_init_svscs<<<Bb, Hh>>>(hh0, cs0);

    int p = 0;
    for (int layer = 0; layer < 2; layer++){
        int q = 1 - p;
        k_avg<<<Bb, Hh>>>(p);
        k_small<<<Bb, Hh>>>(W_fg_g, W_fg_h, W_og_g, W_og_h, W_fgi_g, b_fg, gate_bias, p);
        k_fgi<<<BS/8, Hh>>>(b_fgi, p);
        k_scs<<<Bb, Hh>>>(p, q);
        k_biasmat<<<dim3(7, Bb), Hh>>>(gate_bias, q);
        k_buildXs<<<BS, Hh>>>(p);
        k_mma<<<148, 256, SMEM_MMA>>>();
        k_act<<<BS, Hh>>>(p, q);
        p = q;
    }
    k_avg<<<Bb, Hh>>>(p);
    k_head<<<Bb, Hh>>>(W1, b1, Wout, bout, p, out, out_size);
}

// round 4
// speedup vs baseline: 1.9944x; 1.3875x over previous
#include <cuda_runtime.h>
#include <cuda_bf16.h>
#include <math.h>
#include <stdint.h>

#define Bb 32
#define Ss 512
#define Hh 256
#define BS (Bb*Ss)          // 16384 rows
#define NG 1792             // 7 gates * 256
#define CHK 48              // logical K chunks (64 cols) : K' = 3072
#define SCH 32              // stored K chunks (2048 cols)
#define ABLK (128*128)      // A chunk block bytes (128 rows x 128B) = 16KB
#define BBLK (256*128)      // B chunk block bytes = 32KB
#define NSTG 4
#define STG (ABLK + BBLK)   // 48KB
#define SMEM_MMA (NSTG*STG + 2048)
#define NTILE 896           // 7 (n) x 128 (m)

// ---------------- scratch (device globals; no allocation allowed) ----------------
__device__ float g_wv[BS*Hh];
__device__ float g_hh[2][BS*Hh];
__device__ float g_cs[2][BS*Hh];
__device__ float g_sv[2][Bb*Hh];
__device__ float g_scs[2][Bb*Hh];
__device__ float g_avg[Bb*Hh];
__device__ float g_fgsm[Bb*Hh];
__device__ float g_ogg[Bb*Hh];
__device__ float g_svproj[Bb*Hh];
__device__ float g_biasmat[Bb*NG];
__device__ float g_pre[(size_t)BS*NG];
__device__ float g_sc[BS*Hh];
__device__ float g_Wgt[Hh*NG];         // W_g transposed  [k][g*256+h]
__device__ float g_Wfgih_t[Hh*Hh];     // W_fgi_h^T [k][h]
// chunked, pre-swizzled:  A [128 mtiles][32 chunks][128 rows][64 cols]
__device__ __align__(256) __nv_bfloat16 g_Xs[(size_t)BS*2048];
//                        B [7 ntiles][32 chunks][256 rows][64 cols]
__device__ __align__(256) __nv_bfloat16 g_Wn[(size_t)NG*2048];

__device__ __forceinline__ float sigmoidf(float x){ return 1.f/(1.f+expf(-x)); }

__device__ __forceinline__ uint32_t smem_u32(const void* p){
    uint32_t a;
    asm("{ .reg .u64 t; cvta.to.shared.u64 t, %1; cvt.u32.u64 %0, t; }" : "=r"(a) : "l"(p));
    return a;
}

__device__ __forceinline__ void ldsm4(uint32_t (&r)[4], uint32_t a){
    asm volatile("ldmatrix.sync.aligned.m8n8.x4.shared.b16 {%0,%1,%2,%3}, [%4];"
        : "=r"(r[0]), "=r"(r[1]), "=r"(r[2]), "=r"(r[3]) : "r"(a));
}

__device__ __forceinline__ void mma16816(float (&c)[4], const uint32_t (&a)[4],
                                         uint32_t b0, uint32_t b1){
    asm volatile("mma.sync.aligned.m16n8k16.row.col.f32.bf16.bf16.f32 "
        "{%0,%1,%2,%3}, {%4,%5,%6,%7}, {%8,%9}, {%0,%1,%2,%3};"
        : "+f"(c[0]), "+f"(c[1]), "+f"(c[2]), "+f"(c[3])
        : "r"(a[0]), "r"(a[1]), "r"(a[2]), "r"(a[3]), "r"(b0), "r"(b1));
}

__device__ __forceinline__ void mbar_wait(uint32_t mbar, uint32_t parity){
    uint32_t done;
    asm volatile("{\n\t.reg .pred p;\n\tmbarrier.try_wait.parity.acquire.cta.shared::cta.b64 p, [%1], %2;\n\tselp.b32 %0, 1, 0, p;\n\t}"
        : "=r"(done) : "r"(mbar), "r"(parity) : "memory");
    while (!done){
        asm volatile("{\n\t.reg .pred p;\n\tmbarrier.try_wait.parity.acquire.cta.shared::cta.b64 p, [%1], %2, 0x989680;\n\tselp.b32 %0, 1, 0, p;\n\t}"
            : "=r"(done) : "r"(mbar), "r"(parity) : "memory");
    }
}

// block-wide sum over 256 threads
__device__ __forceinline__ float block_sum_256(float v, float* sbuf){
    int lane = threadIdx.x & 31, w = threadIdx.x >> 5;
    #pragma unroll
    for (int o = 16; o > 0; o >>= 1) v += __shfl_xor_sync(0xffffffffu, v, o);
    if (lane == 0) sbuf[w] = v;
    __syncthreads();
    if (threadIdx.x < 32) {
        float r = (threadIdx.x < 8) ? sbuf[threadIdx.x] : 0.f;
        #pragma unroll
        for (int o = 4; o > 0; o >>= 1) r += __shfl_xor_sync(0xffffffffu, r, o);
        if (threadIdx.x == 0) sbuf[0] = r;
    }
    __syncthreads();
    float out = sbuf[0];
    __syncthreads();
    return out;
}

// ---------------- setup kernels ----------------
__global__ void k_gather(const int* __restrict__ idx, const float* __restrict__ embed){
    int m = blockIdx.x, h = threadIdx.x;
    g_wv[m*Hh + h] = embed[(size_t)idx[m]*Hh + h];
}

__global__ void k_init(const float* __restrict__ hh0, const float* __restrict__ cs0){
    int i = blockIdx.x*Hh + threadIdx.x;
    g_hh[0][i] = hh0[i];
    g_cs[0][i] = cs0[i];
}

__global__ void k_init_svscs(const float* __restrict__ hh0, const float* __restrict__ cs0){
    int b = blockIdx.x, h = threadIdx.x;
    float a = 0.f, c = 0.f;
    for (int s = 0; s < Ss; s++){
        a += hh0[(b*Ss+s)*Hh + h];
        c += cs0[(b*Ss+s)*Hh + h];
    }
    g_sv[0][b*Hh+h]  = a * (1.f/Ss);
    g_scs[0][b*Hh+h] = c * (1.f/Ss);
}

// split W rows into bf16 hi|lo into chunked pre-swizzled layout
__global__ void k_wsplit(const float* __restrict__ W_lr, const float* __restrict__ W_c,
                         const float* __restrict__ W_x){
    int n = blockIdx.x;            // 0..1791
    int g = n >> 8, h = n & 255;
    int ntile = n >> 8;            // wait: careful, ntile is over 1792/256 = 7
    ntile = n / 256;
    int r = n & 255;
    uint32_t sw = (uint32_t)(r & 7) << 4;
    char* base = (char*)g_Wn;
    for (int k = threadIdx.x; k < 1024; k += 256){
        float v;
        if (k < 512)      v = W_lr[((size_t)g*Hh + h)*512 + k];
        else if (k < 768) v = W_c[((size_t)g*Hh + h)*Hh + (k-512)];
        else              v = W_x[((size_t)g*Hh + h)*Hh + (k-768)];
        __nv_bfloat16 hi = __float2bfloat16(v);
        __nv_bfloat16 lo = __float2bfloat16(v - __bfloat162float(hi));
        int chunk = k >> 6;
        uint32_t cb = (uint32_t)((k & 63)*2) ^ sw;
        size_t offHi = ((size_t)(ntile*SCH + chunk))*BBLK + (size_t)r*128 + cb;
        size_t offLo = ((size_t)(ntile*SCH + 16 + chunk))*BBLK + (size_t)r*128 + cb;
        *(__nv_bfloat16*)(base + offHi) = hi;
        *(__nv_bfloat16*)(base + offLo) = lo;
    }
}

__global__ void k_wgt(const float* __restrict__ W_g){
    int k = blockIdx.x, g = blockIdx.y, h = threadIdx.x;
    g_Wgt[(size_t)k*NG + g*Hh + h] = W_g[((size_t)(g*Hh+h))*Hh + k];
}

__global__ void k_wfgih(const float* __restrict__ W_fgi_h){
    int k = blockIdx.x, h = threadIdx.x;
    g_Wfgih_t[k*Hh + h] = W_fgi_h[h*Hh + k];
}

// ---------------- per-layer kernels ----------------
__global__ void k_avg(int p){
    int b = blockIdx.x, h = threadIdx.x;
    const float* hh = g_hh[p];
    float a = 0.f;
    for (int s = 0; s < Ss; s++) a += hh[(b*Ss+s)*Hh + h];
    g_avg[b*Hh+h] = a * (1.f/Ss);
}

__global__ void k_small(const float* __restrict__ W_fg_g, const float* __restrict__ W_fg_h,
                        const float* __restrict__ W_og_g, const float* __restrict__ W_og_h,
                        const float* __restrict__ W_fgi_g, const float* __restrict__ b_fg,
                        const float* __restrict__ gate_bias, int p){
    __shared__ float ssv[Hh], sav[Hh];
    __shared__ float red[32];
    int b = blockIdx.x, h = threadIdx.x;
    ssv[h] = g_sv[p][b*Hh+h];
    sav[h] = g_avg[b*Hh+h];
    __syncthreads();
    float f  = b_fg[h];
    float o  = gate_bias[5*Hh + h];
    float sp = 0.f;
    const float* wfg = W_fg_g  + (size_t)h*Hh;
    const float* wfh = W_fg_h  + (size_t)h*Hh;
    const float* wog = W_og_g  + (size_t)h*Hh;
    const float* woh = W_og_h  + (size_t)h*Hh;
    const float* wfi = W_fgi_g + (size_t)h*Hh;
    for (int k = 0; k < Hh; k++){
        float s = ssv[k], a = sav[k];
        f  += s*wfg[k] + a*wfh[k];
        o  += s*wog[k] + a*woh[k];
        sp += s*wfi[k];
    }
    f = sigmoidf(f);
    o = sigmoidf(o);
    g_ogg[b*Hh+h]    = o;
    g_svproj[b*Hh+h] = sp;
    float e = expf(f);
    float tot = block_sum_256(e, red);
    g_fgsm[b*Hh+h] = e / tot;
}

__global__ void __launch_bounds__(256) k_fgi(const float* __restrict__ b_fgi, int p){
    __shared__ float sh[8][Hh];
    __shared__ float red[32];
    int m0 = blockIdx.x * 8;
    int b  = m0 / Ss;
    int h  = threadIdx.x;
    const float* hh = g_hh[p];
    const float* cs = g_cs[p];
    #pragma unroll
    for (int j = 0; j < 8; j++) sh[j][h] = hh[(m0+j)*Hh + h];
    __syncthreads();
    float base = g_svproj[b*Hh+h] + b_fgi[h];
    float acc[8];
    #pragma unroll
    for (int j = 0; j < 8; j++) acc[j] = base;
    for (int k = 0; k < Hh; k++){
        float w = g_Wfgih_t[k*Hh + h];
        #pragma unroll
        for (int j = 0; j < 8; j++) acc[j] += sh[j][k] * w;
    }
    #pragma unroll
    for (int j = 0; j < 8; j++){
        float e = __expf(__fdividef(1.f, 1.f + __expf(-acc[j])));
        float tot = block_sum_256(e, red);
        g_sc[(m0+j)*Hh + h] = __fdividef(e, tot) * cs[(m0+j)*Hh + h];
    }
}

__global__ void k_scs(int p, int q){
    int b = blockIdx.x, h = threadIdx.x;
    float acc = 0.f;
    for (int s = 0; s < Ss; s++) acc += g_sc[(b*Ss+s)*Hh + h];
    int i = b*Hh + h;
    float ns = g_fgsm[i] * g_scs[p][i] + acc;
    g_scs[q][i] = ns;
    g_sv[q][i]  = g_ogg[i] * tanhf(ns);
}

__global__ void k_biasmat(const float* __restrict__ gate_bias, int q){
    __shared__ float ssv[Hh];
    int g = blockIdx.x, b = blockIdx.y, h = threadIdx.x;
    ssv[h] = g_sv[q][b*Hh + h];
    __syncthreads();
    int n = g*Hh + h;
    float acc = gate_bias[n];
    for (int k = 0; k < Hh; k++) acc += ssv[k] * g_Wgt[(size_t)k*NG + n];
    g_biasmat[(size_t)b*NG + n] = acc;
}

// X = [hb | ha | hh | wv] -> bf16 hi|lo, chunked pre-swizzled layout
__global__ void k_buildXs(int p){
    int m = blockIdx.x, h = threadIdx.x;
    int s = m % Ss;
    const float* hh = g_hh[p];
    float hb = 0.f, ha = 0.f;
    if (s >= 1)    hb += hh[(m-1)*Hh + h];
    if (s >= 2)    hb += hh[(m-2)*Hh + h];
    if (s+1 < Ss)  ha += hh[(m+1)*Hh + h];
    if (s+2 < Ss)  ha += hh[(m+2)*Hh + h];
    float vals[4];
    vals[0] = hb;
    vals[1] = ha;
    vals[2] = hh[m*Hh + h];
    vals[3] = g_wv[m*Hh + h];
    int mtile = m >> 7, r = m & 127;
    uint32_t sw = (uint32_t)(r & 7) << 4;
    char* base = (char*)g_Xs;
    #pragma unroll
    for (int j = 0; j < 4; j++){
        int c = j*256 + h;                 // logical hi col 0..1023
        __nv_bfloat16 hi = __float2bfloat16(vals[j]);
        __nv_bfloat16 lo = __float2bfloat16(vals[j] - __bfloat162float(hi));
        int chunk = c >> 6;
        uint32_t cb = (uint32_t)((c & 63)*2) ^ sw;
        size_t offHi = ((size_t)(mtile*SCH + chunk))*ABLK + (size_t)r*128 + cb;
        size_t offLo = ((size_t)(mtile*SCH + 16 + chunk))*ABLK + (size_t)r*128 + cb;
        *(__nv_bfloat16*)(base + offHi) = hi;
        *(__nv_bfloat16*)(base + offLo) = lo;
    }
}

// ---------------- bulk-copy HMMA GEMM: pre = Xsplit @ Wsplit^T + biasmat ----------------
// persistent, tile 128x256, chunk K=64, 4-stage cp.async.bulk + mbarrier pipeline
__global__ void __launch_bounds__(256,1) k_mma(){
    extern __shared__ char smc[];
    uint32_t sb = smem_u32(smc);
    uint32_t dbase = (sb + 1023) & ~1023u;
    uint32_t mb = dbase + NSTG*STG;      // full[4] @ mb, empty[4] @ mb+32
    int tid = threadIdx.x, wid = tid >> 5, lane = tid & 31;
    int wm = wid >> 2, wn = wid & 3;

    if (tid == 0){
        #pragma unroll
        for (int s = 0; s < NSTG; s++){
            asm volatile("mbarrier.init.shared.b64 [%0], %1;" :: "r"(mb + s*8), "r"(1) : "memory");
            asm volatile("mbarrier.init.shared.b64 [%0], %1;" :: "r"(mb + 32 + s*8), "r"(8) : "memory");
        }
    }
    __syncthreads();

    // fragment address precalc
    uint32_t lh16 = (uint32_t)(lane >> 4) << 4;          // A col-chunk select
    uint32_t lb16 = (uint32_t)((lane >> 3) & 1) << 4;    // B col-chunk select
    uint32_t aPre[4], aSwm[4], bPre[4], bSwm[4];
    #pragma unroll
    for (int mi = 0; mi < 4; mi++){
        int row = wm*64 + mi*16 + (lane & 15);
        aPre[mi] = (uint32_t)row*128;
        aSwm[mi] = (uint32_t)(row & 7) << 4;
    }
    #pragma unroll
    for (int nj = 0; nj < 4; nj++){
        int row = wn*64 + nj*16 + ((lane >> 4) << 3) + (lane & 7);
        bPre[nj] = (uint32_t)row*128;
        bSwm[nj] = (uint32_t)(row & 7) << 4;
    }

    auto issue = [&](int G){
        int cc = G / CHK;
        int tl = blockIdx.x + 148*cc;
        if (tl >= NTILE) return;
        int t = G % CHK;
        int s = G & 3;
        int bm = tl / 7, bn = tl % 7;
        int ach = (t < 32) ? t : (t - 32);
        int bch = (t < 16) ? t : (t - 16);
        const char* srcA = (const char*)g_Xs + ((size_t)(bm*SCH + ach))*ABLK;
        const char* srcB = (const char*)g_Wn + ((size_t)(bn*SCH + bch))*BBLK;
        uint32_t fb = mb + s*8;
        uint32_t dA = dbase + s*STG;
        uint32_t dB = dA + ABLK;
        asm volatile("mbarrier.arrive.expect_tx.shared.b64 _, [%0], %1;"
                     :: "r"(fb), "r"((uint32_t)STG) : "memory");
        asm volatile("cp.async.bulk.shared::cta.global.mbarrier::complete_tx::bytes [%0], [%1], %2, [%3];"
                     :: "r"(dA), "l"(srcA), "r"((uint32_t)ABLK), "r"(fb) : "memory");
        asm volatile("cp.async.bulk.shared::cta.global.mbarrier::complete_tx::bytes [%0], [%1], %2, [%3];"
                     :: "r"(dB), "l"(srcB), "r"((uint32_t)BBLK), "r"(fb) : "memory");
    };

    if (tid == 0){
        #pragma unroll
        for (int g = 0; g < NSTG; g++) issue(g);
    }

    int c = 0;
    for (int tile = blockIdx.x; tile < NTILE; tile += 148, c++){
        int bm = tile / 7, bn = tile % 7;

        float acc[4][8][4];
        #pragma unroll
        for (int i = 0; i < 4; i++)
            #pragma unroll
            for (int j = 0; j < 8; j++)
                #pragma unroll
                for (int r = 0; r < 4; r++) acc[i][j][r] = 0.f;

        for (int t = 0; t < CHK; t++){
            int G = c*CHK + t;
            int s = G & 3;
            uint32_t par = (uint32_t)(G >> 2) & 1u;
            mbar_wait(mb + s*8, par);

            uint32_t stA = dbase + s*STG;
            uint32_t stB = stA + ABLK;
            #pragma unroll
            for (int ks = 0; ks < 4; ks++){
                uint32_t afr[4][4], bfr[4][4];
                uint32_t ca = (uint32_t)(ks*32) + lh16;
                uint32_t cb = (uint32_t)(ks*32) + lb16;
                #pragma unroll
                for (int mi = 0; mi < 4; mi++)
                    ldsm4(afr[mi], stA + aPre[mi] + (ca ^ aSwm[mi]));
                #pragma unroll
                for (int nj = 0; nj < 4; nj++)
                    ldsm4(bfr[nj], stB + bPre[nj] + (cb ^ bSwm[nj]));
                #pragma unroll
                for (int mi = 0; mi < 4; mi++){
                    #pragma unroll
                    for (int nj = 0; nj < 4; nj++){
                        mma16816(acc[mi][2*nj],   afr[mi], bfr[nj][0], bfr[nj][1]);
                        mma16816(acc[mi][2*nj+1], afr[mi], bfr[nj][2], bfr[nj][3]);
                    }
                }
            }

            if (lane == 0)
                asm volatile("mbarrier.arrive.shared.b64 _, [%0];" :: "r"(mb + 32 + s*8) : "memory");
            if (tid == 0){
                mbar_wait(mb + 32 + s*8, par);
                issue(G + NSTG);
            }
        }

        // epilogue: add biasmat, store fp32
        int b = bm >> 2;                       // 4 M-tiles per batch row
        int colbase = bn*256 + wn*64;
        const float* bias = g_biasmat + (size_t)b*NG + colbase;
        #pragma unroll
        for (int mi = 0; mi < 4; mi++){
            int r0 = bm*128 + wm*64 + mi*16 + (lane >> 2);
            float* out0 = g_pre + (size_t)r0*NG + colbase;
            float* out1 = g_pre + (size_t)(r0+8)*NG + colbase;
            #pragma unroll
            for (int nj = 0; nj < 8; nj++){
                int col = nj*8 + (lane & 3)*2;
                float2 bv = *(const float2*)(bias + col);
                float2 o0, o1;
                o0.x = acc[mi][nj][0] + bv.x; o0.y = acc[mi][nj][1] + bv.y;
                o1.x = acc[mi][nj][2] + bv.x; o1.y = acc[mi][nj][3] + bv.y;
                *(float2*)(out0 + col) = o0;
                *(float2*)(out1 + col) = o1;
            }
        }
    }
}

// activations + state update
__global__ void k_act(int p, int q){
    __shared__ float red[32];
    int m = blockIdx.x, h = threadIdx.x;
    int b = m / Ss, s = m % Ss;
    const float* pr = g_pre + (size_t)m*NG;
    float eg[5];
    float esum = 0.f;
    #pragma unroll
    for (int g = 0; g < 5; g++){
        float v = __fdividef(1.f, 1.f + __expf(-pr[g*Hh + h]));
        eg[g] = __expf(v);
        esum += eg[g];
    }
    float og = __fdividef(1.f, 1.f + __expf(-pr[5*Hh + h]));
    float u  = tanhf(pr[6*Hh + h]);
    float tot = block_sum_256(esum, red);
    float inv = __fdividef(1.f, tot);
    const float* cs = g_cs[p];
    float cb = 0.f, ca = 0.f;
    if (s >= 1)   cb += cs[(m-1)*Hh + h];
    if (s >= 2)   cb += cs[(m-2)*Hh + h];
    if (s+1 < Ss) ca += cs[(m+1)*Hh + h];
    if (s+2 < Ss) ca += cs[(m+2)*Hh + h];
    float i_t = eg[0]*inv, l_t = eg[1]*inv, r_t = eg[2]*inv, f_t = eg[3]*inv, s_t = eg[4]*inv;
    float ncs = l_t*cb + f_t*cs[m*Hh+h] + r_t*ca + s_t*g_scs[p][b*Hh+h] + i_t*u;
    g_cs[q][m*Hh+h] = ncs;
    g_hh[q][m*Hh+h] = og * tanhf(ncs);
}

// output head
__global__ void k_head(const float* __restrict__ W1, const float* __restrict__ b1,
                       const float* __restrict__ Wout, const float* __restrict__ bout,
                       int p, float* __restrict__ out, int out_size){
    __shared__ float sa[Hh], ssv[Hh], conc[Hh], fc[5];
    __shared__ float lse;
    int b = blockIdx.x, h = threadIdx.x;
    sa[h]  = g_avg[b*Hh + h];
    ssv[h] = g_sv[p][b*Hh + h];
    __syncthreads();
    float c = b1[h];
    const float* w = W1 + (size_t)h*512;
    for (int k = 0; k < Hh; k++) c += sa[k]  * w[k];
    for (int k = 0; k < Hh; k++) c += ssv[k] * w[256 + k];
    conc[h] = c;
    __syncthreads();
    if (h < 5){
        float f = bout[h];
        const float* wo = Wout + (size_t)h*Hh;
        for (int k = 0; k < Hh; k++) f += conc[k]*wo[k];
        fc[h] = f;
    }
    __syncthreads();
    if (h == 0){
        float mx = fc[0];
        #pragma unroll
        for (int i = 1; i < 5; i++) mx = fmaxf(mx, fc[i]);
        float sum = 0.f;
        #pragma unroll
        for (int i = 0; i < 5; i++) sum += expf(fc[i] - mx);
        lse = mx + logf(sum);
    }
    __syncthreads();
    if (h < 5 && out_size >= Bb*5) out[b*5 + h] = fc[h] - lse;
    if (out_size >= Bb*5 + Bb*Hh)  out[Bb*5 + b*Hh + h] = ssv[h];
}

// ---------------- host ----------------
extern "C" void kernel_launch(void* const* d_in, const int* in_sizes, int n_in,
                              void* d_out, int out_size){
    const int*   idx       = (const int*)  d_in[0];
    const float* hh0       = (const float*)d_in[2];
    const float* cs0       = (const float*)d_in[3];
    const float* embed     = (const float*)d_in[4];
    const float* W_lr      = (const float*)d_in[5];
    const float* W_c       = (const float*)d_in[6];
    const float* W_x       = (const float*)d_in[7];
    const float* W_g       = (const float*)d_in[8];
    const float* gate_bias = (const float*)d_in[9];
    const float* W_fg_g    = (const float*)d_in[10];
    const float* W_fg_h    = (const float*)d_in[11];
    const float* W_fgi_g   = (const float*)d_in[12];
    const float* W_fgi_h   = (const float*)d_in[13];
    const float* W_og_g    = (const float*)d_in[14];
    const float* W_og_h    = (const float*)d_in[15];
    const float* b_fg      = (const float*)d_in[16];
    const float* b_fgi     = (const float*)d_in[17];
    const float* W1        = (const float*)d_in[18];
    const float* b1        = (const float*)d_in[19];
    const float* Wout      = (const float*)d_in[20];
    const float* bout      = (const float*)d_in[21];
    float* out = (float*)d_out;

    cudaFuncSetAttribute(k_mma, cudaFuncAttributeMaxDynamicSharedMemorySize, SMEM_MMA);

    k_gather<<<BS, Hh>>>(idx, embed);
    k_wsplit<<<NG, 256>>>(W_lr, W_c, W_x);
    k_wgt<<<dim3(Hh, 7), Hh>>>(W_g);
    k_wfgih<<<Hh, Hh>>>(W_fgi_h);
    k_init<<<BS, Hh>>>(hh0, cs0);
    k_init_svscs<<<Bb, Hh>>>(hh0, cs0);

    int p = 0;
    for (int layer = 0; layer < 2; layer++){
        int q = 1 - p;
        k_avg<<<Bb, Hh>>>(p);
        k_small<<<Bb, Hh>>>(W_fg_g, W_fg_h, W_og_g, W_og_h, W_fgi_g, b_fg, gate_bias, p);
        k_fgi<<<BS/8, Hh>>>(b_fgi, p);
        k_scs<<<Bb, Hh>>>(p, q);
        k_biasmat<<<dim3(7, Bb), Hh>>>(gate_bias, q);
        k_buildXs<<<BS, Hh>>>(p);
        k_mma<<<148, 256, SMEM_MMA>>>();
        k_act<<<BS, Hh>>>(p, q);
        p = q;
    }
    k_avg<<<Bb, Hh>>>(p);
    k_head<<<Bb, Hh>>>(W1, b1, Wout, bout, p, out, out_size);
}